// round 4
// baseline (speedup 1.0000x reference)
#include <cuda_runtime.h>
#include <cuda_bf16.h>
#include <cstdint>

static constexpr int NB  = 2;
static constexpr int S   = 4096;
static constexpr int CIN = 2048;
static constexpr int RC  = 512;
static constexpr int OC  = 4096;
static constexpr int KCH  = 8;
static constexpr int KSEG = S / KCH;

// ---------------- device scratch (bf16 hi/lo planes) ------------------------
__device__ __align__(16) __nv_bfloat16 g_xh [(size_t)NB * CIN * S];
__device__ __align__(16) __nv_bfloat16 g_xl [(size_t)NB * CIN * S];
__device__ __align__(16) __nv_bfloat16 g_wrh[(size_t)RC * CIN];
__device__ __align__(16) __nv_bfloat16 g_wrl[(size_t)RC * CIN];
__device__ __align__(16) __nv_bfloat16 g_w1h[(size_t)RC * RC];
__device__ __align__(16) __nv_bfloat16 g_w1l[(size_t)RC * RC];
__device__ __align__(16) __nv_bfloat16 g_w2h[(size_t)OC * RC];
__device__ __align__(16) __nv_bfloat16 g_w2l[(size_t)OC * RC];
__device__ __align__(16) __nv_bfloat16 g_redh[(size_t)NB * RC * S];
__device__ __align__(16) __nv_bfloat16 g_redl[(size_t)NB * RC * S];
__device__ __align__(16) __nv_bfloat16 g_hh [(size_t)NB * RC * S];
__device__ __align__(16) __nv_bfloat16 g_hl [(size_t)NB * RC * S];
__device__ __align__(16) __nv_bfloat16 g_ah [(size_t)NB * OC * S];
__device__ __align__(16) __nv_bfloat16 g_al [(size_t)NB * OC * S];
__device__ float g_m [NB * S];
__device__ float g_z [NB * S];
__device__ float g_pm[KCH * NB * S];
__device__ float g_pz[KCH * NB * S];

// ---------------- helpers ----------------------------------------------------
#define SW(o) ((o) ^ (((o) >> 3) & 0x70))

__device__ __forceinline__ uint32_t s2u(const void* p) {
    uint32_t a;
    asm("{ .reg .u64 t; cvta.to.shared.u64 t, %1; cvt.u32.u64 %0, t; }"
        : "=r"(a) : "l"(p));
    return a;
}

__device__ __forceinline__ void cpa16(uint32_t s, const void* g) {
    asm volatile("cp.async.cg.shared.global [%0], [%1], 16;" :: "r"(s), "l"(g));
}

#define CP_COMMIT() asm volatile("cp.async.commit_group;" ::: "memory")
#define CP_WAIT0()  asm volatile("cp.async.wait_group 0;" ::: "memory")
#define CP_WAIT1()  asm volatile("cp.async.wait_group 1;" ::: "memory")

#define LDSM4(r, a)                                                            \
    asm volatile("ldmatrix.sync.aligned.m8n8.x4.shared.b16 {%0,%1,%2,%3}, [%4];" \
                 : "=r"((r)[0]), "=r"((r)[1]), "=r"((r)[2]), "=r"((r)[3])      \
                 : "r"(a))

#define LDSM2T(r, a)                                                           \
    asm volatile("ldmatrix.sync.aligned.m8n8.x2.trans.shared.b16 {%0,%1}, [%2];" \
                 : "=r"((r)[0]), "=r"((r)[1]) : "r"(a))

__device__ __forceinline__ void mma16816(float* d, const uint32_t* a,
                                         const uint32_t* b) {
    asm volatile(
        "mma.sync.aligned.m16n8k16.row.col.f32.bf16.bf16.f32 "
        "{%0,%1,%2,%3}, {%4,%5,%6,%7}, {%8,%9}, {%0,%1,%2,%3};"
        : "+f"(d[0]), "+f"(d[1]), "+f"(d[2]), "+f"(d[3])
        : "r"(a[0]), "r"(a[1]), "r"(a[2]), "r"(a[3]), "r"(b[0]), "r"(b[1]));
}

// split fp32 pair into packed bf16 hi plane + lo plane
__device__ __forceinline__ void split2(float a, float b, uint32_t& h, uint32_t& l) {
    uint32_t hh;
    asm("cvt.rn.bf16x2.f32 %0, %1, %2;" : "=r"(hh) : "f"(b), "f"(a));
    float ah = __uint_as_float(hh << 16);
    float bh = __uint_as_float(hh & 0xffff0000u);
    float ar = a - ah;
    float br = b - bh;
    asm("cvt.rn.bf16x2.f32 %0, %1, %2;" : "=r"(l) : "f"(br), "f"(ar));
    h = hh;
}

// SMEM layout: 3 stages x (AHI 16K | ALO 16K | BHI 16K | BLO 16K)
static constexpr int STG    = 65536;
static constexpr int OFF_AHI = 0;
static constexpr int OFF_ALO = 16384;
static constexpr int OFF_BHI = 32768;
static constexpr int OFF_BLO = 49152;
static constexpr int SMEM_BYTES = 3 * STG;   // 196608

enum { EPL_BNRELU = 0, EPL_PLAIN = 1, EPF_DIV = 2 };

// ============== split-bf16 tensor GEMM: C = (Ahi+Alo)(Bhi+Blo) ===============
template <int EP>
__global__ void __launch_bounds__(256, 1)
gemm_mma(const __nv_bfloat16* __restrict__ Ahi, const __nv_bfloat16* __restrict__ Alo,
         const __nv_bfloat16* __restrict__ Bhi, const __nv_bfloat16* __restrict__ Blo,
         float* __restrict__ Cf,
         __nv_bfloat16* __restrict__ Chi, __nv_bfloat16* __restrict__ Clo,
         int M, int K, int N,
         size_t aBS, size_t bBS, size_t cBS,
         const float* __restrict__ bnp, const float* __restrict__ zcol)
{
    extern __shared__ char smem[];
    const uint32_t sb = s2u(smem);
    const int t = threadIdx.x, wid = t >> 5, lane = t & 31;
    const int bz = blockIdx.z;
    const int m0 = blockIdx.y * 128, n0 = blockIdx.x * 128;
    const int wm0 = (wid >> 2) * 64, wn0 = (wid & 3) * 32;

    const __nv_bfloat16* Abh = Ahi + bz * aBS + (size_t)m0 * K;
    const __nv_bfloat16* Abl = Alo + bz * aBS + (size_t)m0 * K;
    const __nv_bfloat16* Bbh = Bhi + bz * bBS + n0;
    const __nv_bfloat16* Bbl = Blo + bz * bBS + n0;

    // per-thread load plan
    const int a_r = t >> 3, a_c = t & 7;
    const int b_k = t >> 4, b_h = (t >> 3) & 1, b_c = t & 7;

    auto load_chunk = [&](int k0, int stg) {
        const uint32_t st = sb + stg * STG;
#pragma unroll
        for (int it = 0; it < 4; it++) {
            int row = it * 32 + a_r;
            uint32_t d = (uint32_t)SW(row * 128 + a_c * 16);
            size_t so = (size_t)row * K + k0 + a_c * 8;
            cpa16(st + OFF_AHI + d, Abh + so);
            cpa16(st + OFF_ALO + d, Abl + so);
        }
#pragma unroll
        for (int it = 0; it < 4; it++) {
            int k = it * 16 + b_k;
            uint32_t d = (uint32_t)(b_h * 8192 + SW(k * 128 + b_c * 16));
            size_t so = (size_t)(k0 + k) * N + b_h * 64 + b_c * 8;
            cpa16(st + OFF_BHI + d, Bbh + so);
            cpa16(st + OFF_BLO + d, Bbl + so);
        }
        CP_COMMIT();
    };

    float acc[4][4][4];
#pragma unroll
    for (int i = 0; i < 4; i++)
#pragma unroll
        for (int j = 0; j < 4; j++)
#pragma unroll
            for (int q = 0; q < 4; q++) acc[i][j][q] = 0.f;

    const int la_row = lane & 15;
    const int la_kc  = (lane >> 4) * 8;

    const int nc = K / 64;
    load_chunk(0, 0);
    if (nc > 1) load_chunk(64, 1);

    int stg = 0;
    for (int ci = 0; ci < nc; ci++) {
        if (ci + 1 < nc) { CP_WAIT1(); } else { CP_WAIT0(); }
        __syncthreads();
        if (ci + 2 < nc) {
            int s2 = stg + 2; if (s2 >= 3) s2 -= 3;
            load_chunk((ci + 2) * 64, s2);
        }

        const uint32_t st = sb + stg * STG;
#pragma unroll
        for (int ks = 0; ks < 4; ks++) {
            uint32_t ahi[4][4], alo[4][4], bhi[4][2], blo[4][2];
#pragma unroll
            for (int i = 0; i < 4; i++) {
                uint32_t d = (uint32_t)SW((wm0 + 16 * i + la_row) * 128 +
                                          (ks * 16 + la_kc) * 2);
                LDSM4(ahi[i], st + OFF_AHI + d);
                LDSM4(alo[i], st + OFF_ALO + d);
            }
#pragma unroll
            for (int j = 0; j < 4; j++) {
                int col = wn0 + 8 * j;
                uint32_t d = (uint32_t)((col >> 6) * 8192 +
                                        SW((ks * 16 + la_row) * 128 + (col & 63) * 2));
                LDSM2T(bhi[j], st + OFF_BHI + d);
                LDSM2T(blo[j], st + OFF_BLO + d);
            }
            // product-outer order: 16 independent mma between accumulator reuse
#pragma unroll
            for (int i = 0; i < 4; i++)
#pragma unroll
                for (int j = 0; j < 4; j++)
                    mma16816(acc[i][j], ahi[i], bhi[j]);
#pragma unroll
            for (int i = 0; i < 4; i++)
#pragma unroll
                for (int j = 0; j < 4; j++)
                    mma16816(acc[i][j], ahi[i], blo[j]);
#pragma unroll
            for (int i = 0; i < 4; i++)
#pragma unroll
                for (int j = 0; j < 4; j++)
                    mma16816(acc[i][j], alo[i], bhi[j]);
        }
        stg++; if (stg >= 3) stg -= 3;
    }
    __syncthreads();

    // ---------------- epilogue ----------------
    const int g  = lane >> 2;
    const int t2 = lane & 3;

#pragma unroll
    for (int i = 0; i < 4; i++) {
        const int r0 = m0 + wm0 + 16 * i + g;
        const int r1 = r0 + 8;
        float sc0 = 1.f, sh0 = 0.f, sc1 = 1.f, sh1 = 0.f;
        if (EP == EPL_BNRELU) {
            float ga = bnp[r0], be = bnp[M + r0], mu = bnp[2 * M + r0], va = bnp[3 * M + r0];
            sc0 = ga * rsqrtf(va + 1e-5f);
            sh0 = be - mu * sc0;
            ga = bnp[r1]; be = bnp[M + r1]; mu = bnp[2 * M + r1]; va = bnp[3 * M + r1];
            sc1 = ga * rsqrtf(va + 1e-5f);
            sh1 = be - mu * sc1;
        }
#pragma unroll
        for (int j = 0; j < 4; j++) {
            const int c = n0 + wn0 + 8 * j + t2 * 2;
            float v0 = acc[i][j][0], v1 = acc[i][j][1];
            float v2 = acc[i][j][2], v3 = acc[i][j][3];
            if (EP == EPL_BNRELU) {
                v0 = fmaxf(v0 * sc0 + sh0, 0.f);
                v1 = fmaxf(v1 * sc0 + sh0, 0.f);
                v2 = fmaxf(v2 * sc1 + sh1, 0.f);
                v3 = fmaxf(v3 * sc1 + sh1, 0.f);
            }
            if (EP == EPF_DIV) {
                const float* zb = zcol + (size_t)bz * N + c;
                float z0 = zb[0], z1 = zb[1];
                float2* Cr0 = (float2*)(Cf + bz * cBS + (size_t)r0 * N + c);
                float2* Cr1 = (float2*)(Cf + bz * cBS + (size_t)r1 * N + c);
                *Cr0 = make_float2(v0 / z0, v1 / z1);
                *Cr1 = make_float2(v2 / z0, v3 / z1);
            } else {
                uint32_t h0, l0, h1, l1;
                split2(v0, v1, h0, l0);
                split2(v2, v3, h1, l1);
                size_t cb0 = bz * cBS + (size_t)r0 * N + c;
                size_t cb1 = bz * cBS + (size_t)r1 * N + c;
                *(uint32_t*)(Chi + cb0) = h0;
                *(uint32_t*)(Clo + cb0) = l0;
                *(uint32_t*)(Chi + cb1) = h1;
                *(uint32_t*)(Clo + cb1) = l1;
            }
        }
    }
}

// ================= fp32 -> bf16 hi/lo plane conversion ======================
__global__ void to_planes(const float4* __restrict__ src,
                          uint2* __restrict__ hi, uint2* __restrict__ lo, int n4)
{
    int i = blockIdx.x * blockDim.x + threadIdx.x;
    if (i >= n4) return;
    float4 f = src[i];
    uint2 h, l;
    split2(f.x, f.y, h.x, l.x);
    split2(f.z, f.w, h.y, l.y);
    hi[i] = h;
    lo[i] = l;
}

// ================= softmax stats over a-planes ==============================
__global__ void colmax_part(const __nv_bfloat16* __restrict__ ah, float* __restrict__ pm)
{
    const int n  = blockIdx.z;
    const int tc = blockIdx.x * blockDim.x + threadIdx.x;
    const int kc = blockIdx.y;
    const __nv_bfloat16* p = ah + (size_t)n * S * S + (size_t)kc * KSEG * S + tc;
    float mx = -3.402823466e38f;
#pragma unroll 8
    for (int k = 0; k < KSEG; k++)
        mx = fmaxf(mx, __bfloat162float(p[(size_t)k * S]));
    pm[(size_t)kc * (NB * S) + n * S + tc] = mx;
}

template <bool IS_MAX>
__global__ void reduce_parts(const float* __restrict__ part, float* __restrict__ outv)
{
    const int i = blockIdx.x * blockDim.x + threadIdx.x;
    if (i >= NB * S) return;
    float v = IS_MAX ? -3.402823466e38f : 0.f;
#pragma unroll
    for (int c = 0; c < KCH; c++) {
        float p = part[(size_t)c * (NB * S) + i];
        v = IS_MAX ? fmaxf(v, p) : (v + p);
    }
    outv[i] = v;
}

__global__ void expsum_part(__nv_bfloat16* __restrict__ ah, __nv_bfloat16* __restrict__ al,
                            const float* __restrict__ m, float* __restrict__ pz)
{
    const int n  = blockIdx.z;
    const int tc = blockIdx.x * blockDim.x + threadIdx.x;
    const int kc = blockIdx.y;
    const float mv = m[n * S + tc];
    const size_t base = (size_t)n * S * S + (size_t)kc * KSEG * S + tc;
    float s = 0.f;
#pragma unroll 4
    for (int k = 0; k < KSEG; k++) {
        size_t idx = base + (size_t)k * S;
        float f = __bfloat162float(ah[idx]) + __bfloat162float(al[idx]);
        float v = __expf(f - mv);
        s += v;
        __nv_bfloat16 vh = __float2bfloat16(v);
        float vr = v - __bfloat162float(vh);
        ah[idx] = vh;
        al[idx] = __float2bfloat16(vr);
    }
    pz[(size_t)kc * (NB * S) + n * S + tc] = s;
}

// ================= launch ====================================================
extern "C" void kernel_launch(void* const* d_in, const int* in_sizes, int n_in,
                              void* d_out, int out_size)
{
    (void)in_sizes; (void)n_in; (void)out_size;
    const float* x = (const float*)d_in[0];
    float* out = (float*)d_out;

    __nv_bfloat16 *xh, *xl, *wrh, *wrl, *w1h, *w1l, *w2h, *w2l;
    __nv_bfloat16 *redh, *redl, *hh, *hl, *ah, *al;
    float *m_, *z_, *pm_, *pz_;
    cudaGetSymbolAddress((void**)&xh, g_xh);   cudaGetSymbolAddress((void**)&xl, g_xl);
    cudaGetSymbolAddress((void**)&wrh, g_wrh); cudaGetSymbolAddress((void**)&wrl, g_wrl);
    cudaGetSymbolAddress((void**)&w1h, g_w1h); cudaGetSymbolAddress((void**)&w1l, g_w1l);
    cudaGetSymbolAddress((void**)&w2h, g_w2h); cudaGetSymbolAddress((void**)&w2l, g_w2l);
    cudaGetSymbolAddress((void**)&redh, g_redh); cudaGetSymbolAddress((void**)&redl, g_redl);
    cudaGetSymbolAddress((void**)&hh, g_hh);   cudaGetSymbolAddress((void**)&hl, g_hl);
    cudaGetSymbolAddress((void**)&ah, g_ah);   cudaGetSymbolAddress((void**)&al, g_al);
    cudaGetSymbolAddress((void**)&m_, g_m);    cudaGetSymbolAddress((void**)&z_, g_z);
    cudaGetSymbolAddress((void**)&pm_, g_pm);  cudaGetSymbolAddress((void**)&pz_, g_pz);

    cudaFuncSetAttribute(gemm_mma<EPL_BNRELU>, cudaFuncAttributeMaxDynamicSharedMemorySize, SMEM_BYTES);
    cudaFuncSetAttribute(gemm_mma<EPL_PLAIN>,  cudaFuncAttributeMaxDynamicSharedMemorySize, SMEM_BYTES);
    cudaFuncSetAttribute(gemm_mma<EPF_DIV>,    cudaFuncAttributeMaxDynamicSharedMemorySize, SMEM_BYTES);

    // x -> planes (once per call)
    {
        int n4 = NB * CIN * S / 4;
        to_planes<<<(n4 + 255) / 256, 256>>>((const float4*)x, (uint2*)xh, (uint2*)xl, n4);
    }

    for (int br = 0; br < 2; br++) {
        const float* wred = (const float*)d_in[1 + br * 5 + 0];
        const float* bn1  = (const float*)d_in[1 + br * 5 + 1];
        const float* w1   = (const float*)d_in[1 + br * 5 + 2];
        const float* bn2  = (const float*)d_in[1 + br * 5 + 3];
        const float* w2   = (const float*)d_in[1 + br * 5 + 4];

        {
            int n4 = RC * CIN / 4;
            to_planes<<<(n4 + 255) / 256, 256>>>((const float4*)wred, (uint2*)wrh, (uint2*)wrl, n4);
            n4 = RC * RC / 4;
            to_planes<<<(n4 + 255) / 256, 256>>>((const float4*)w1, (uint2*)w1h, (uint2*)w1l, n4);
            n4 = OC * RC / 4;
            to_planes<<<(n4 + 255) / 256, 256>>>((const float4*)w2, (uint2*)w2h, (uint2*)w2l, n4);
        }

        // red = relu(bn1(wred @ x))  -> planes
        gemm_mma<EPL_BNRELU><<<dim3(S / 128, RC / 128, NB), 256, SMEM_BYTES>>>(
            wrh, wrl, xh, xl, nullptr, redh, redl,
            RC, CIN, S, 0, (size_t)CIN * S, (size_t)RC * S, bn1, nullptr);

        // h = relu(bn2(w1 @ red))   -> planes
        gemm_mma<EPL_BNRELU><<<dim3(S / 128, RC / 128, NB), 256, SMEM_BYTES>>>(
            w1h, w1l, redh, redl, nullptr, hh, hl,
            RC, RC, S, 0, (size_t)RC * S, (size_t)RC * S, bn2, nullptr);

        // a = w2 @ h                -> planes
        gemm_mma<EPL_PLAIN><<<dim3(S / 128, OC / 128, NB), 256, SMEM_BYTES>>>(
            w2h, w2l, hh, hl, nullptr, ah, al,
            OC, RC, S, 0, (size_t)RC * S, (size_t)OC * S, nullptr, nullptr);

        // deterministic column softmax, exp in place
        colmax_part<<<dim3(S / 256, KCH, NB), 256>>>(ah, pm_);
        reduce_parts<true><<<(NB * S + 255) / 256, 256>>>(pm_, m_);
        expsum_part<<<dim3(S / 256, KCH, NB), 256>>>(ah, al, m_, pz_);
        reduce_parts<false><<<(NB * S + 255) / 256, 256>>>(pz_, z_);

        // fm = red @ exp(a-m) / Z   -> fp32 out slice
        gemm_mma<EPF_DIV><<<dim3(S / 128, RC / 128, NB), 256, SMEM_BYTES>>>(
            redh, redl, ah, al, out + (size_t)br * RC * S, nullptr, nullptr,
            RC, S, S, (size_t)RC * S, (size_t)S * S, (size_t)2 * RC * S,
            nullptr, z_);
    }
}

// round 5
// speedup vs baseline: 1.3238x; 1.3238x over previous
#include <cuda_runtime.h>
#include <cuda_bf16.h>
#include <cstdint>

static constexpr int NB  = 2;
static constexpr int S   = 4096;
static constexpr int CIN = 2048;
static constexpr int RC  = 512;
static constexpr int OC  = 4096;
static constexpr int KCH  = 8;
static constexpr int KSEG = S / KCH;
static constexpr int NZ   = 2 * NB;   // branches x batch

// ---------------- device scratch (bf16 hi/lo planes) ------------------------
__device__ __align__(16) __nv_bfloat16 g_xh [(size_t)NB * CIN * S];
__device__ __align__(16) __nv_bfloat16 g_xl [(size_t)NB * CIN * S];
__device__ __align__(16) __nv_bfloat16 g_wrh[2][(size_t)RC * CIN];
__device__ __align__(16) __nv_bfloat16 g_wrl[2][(size_t)RC * CIN];
__device__ __align__(16) __nv_bfloat16 g_w1h[2][(size_t)RC * RC];
__device__ __align__(16) __nv_bfloat16 g_w1l[2][(size_t)RC * RC];
__device__ __align__(16) __nv_bfloat16 g_w2h[2][(size_t)OC * RC];
__device__ __align__(16) __nv_bfloat16 g_w2l[2][(size_t)OC * RC];
__device__ __align__(16) __nv_bfloat16 g_redh[(size_t)NZ * RC * S];
__device__ __align__(16) __nv_bfloat16 g_redl[(size_t)NZ * RC * S];
__device__ __align__(16) __nv_bfloat16 g_hh [(size_t)NZ * RC * S];
__device__ __align__(16) __nv_bfloat16 g_hl [(size_t)NZ * RC * S];
__device__ __align__(16) __nv_bfloat16 g_ah [(size_t)NZ * OC * S];
__device__ __align__(16) __nv_bfloat16 g_al [(size_t)NZ * OC * S];
__device__ float g_m [NZ * S];
__device__ float g_z [NZ * S];
__device__ float g_pm[KCH * NZ * S];
__device__ float g_pz[KCH * NZ * S];

// ---------------- helpers ----------------------------------------------------
#define SW(o) ((o) ^ (((o) >> 3) & 0x70))

__device__ __forceinline__ uint32_t s2u(const void* p) {
    uint32_t a;
    asm("{ .reg .u64 t; cvta.to.shared.u64 t, %1; cvt.u32.u64 %0, t; }"
        : "=r"(a) : "l"(p));
    return a;
}

__device__ __forceinline__ void cpa16(uint32_t s, const void* g) {
    asm volatile("cp.async.cg.shared.global [%0], [%1], 16;" :: "r"(s), "l"(g));
}

#define CP_COMMIT() asm volatile("cp.async.commit_group;" ::: "memory")
#define CP_WAIT0()  asm volatile("cp.async.wait_group 0;" ::: "memory")

#define LDSM4(r, a)                                                            \
    asm volatile("ldmatrix.sync.aligned.m8n8.x4.shared.b16 {%0,%1,%2,%3}, [%4];" \
                 : "=r"((r)[0]), "=r"((r)[1]), "=r"((r)[2]), "=r"((r)[3])      \
                 : "r"(a))

#define LDSM4T(r, a)                                                           \
    asm volatile("ldmatrix.sync.aligned.m8n8.x4.trans.shared.b16 {%0,%1,%2,%3}, [%4];" \
                 : "=r"((r)[0]), "=r"((r)[1]), "=r"((r)[2]), "=r"((r)[3])      \
                 : "r"(a))

__device__ __forceinline__ void mma16816(float* d, const uint32_t* a,
                                         const uint32_t* b) {
    asm volatile(
        "mma.sync.aligned.m16n8k16.row.col.f32.bf16.bf16.f32 "
        "{%0,%1,%2,%3}, {%4,%5,%6,%7}, {%8,%9}, {%0,%1,%2,%3};"
        : "+f"(d[0]), "+f"(d[1]), "+f"(d[2]), "+f"(d[3])
        : "r"(a[0]), "r"(a[1]), "r"(a[2]), "r"(a[3]), "r"(b[0]), "r"(b[1]));
}

__device__ __forceinline__ void split2(float a, float b, uint32_t& h, uint32_t& l) {
    uint32_t hh;
    asm("cvt.rn.bf16x2.f32 %0, %1, %2;" : "=r"(hh) : "f"(b), "f"(a));
    float ah = __uint_as_float(hh << 16);
    float bh = __uint_as_float(hh & 0xffff0000u);
    float ar = a - ah;
    float br = b - bh;
    asm("cvt.rn.bf16x2.f32 %0, %1, %2;" : "=r"(l) : "f"(br), "f"(ar));
    h = hh;
}

// SMEM stage: AHI 16K | ALO 16K | BHI 8K | BLO 8K = 48K; 2 stages = 96K
static constexpr int STG    = 49152;
static constexpr int OFF_ALO = 16384;
static constexpr int OFF_BHI = 32768;
static constexpr int OFF_BLO = 40960;
static constexpr int SMEM_BYTES = 2 * STG;

enum { EPL_BNRELU = 0, EPL_PLAIN = 1, EPF_DIV = 2 };

struct GP {
    const __nv_bfloat16 *Ah[2], *Al[2], *Bh[2], *Bl[2];
    __nv_bfloat16 *Ch[2], *Cl[2];
    float *Cf[2];
    const float *bn[2], *z[2];
    int M, K, N;
    size_t aBS, bBS, cBS;
};

// ======= split-bf16 tensor GEMM (both branches): C = (Ahi+Alo)(Bhi+Blo) =====
// CTA tile 128x64, 8 warps (4x2), warp tile 32x32, K-chunk 64, 2 CTAs/SM.
template <int EP>
__global__ void __launch_bounds__(256, 2)
gemm_mma(GP p)
{
    extern __shared__ char smem[];
    const uint32_t sb = s2u(smem);
    const int t = threadIdx.x, wid = t >> 5, lane = t & 31;
    const int br = blockIdx.z >> 1, bz = blockIdx.z & 1;
    const int m0 = blockIdx.y * 128, n0 = blockIdx.x * 64;
    const int wm0 = (wid >> 1) * 32, wn0 = (wid & 1) * 32;
    const int K = p.K, N = p.N;

    const __nv_bfloat16* Abh = p.Ah[br] + bz * p.aBS + (size_t)m0 * K;
    const __nv_bfloat16* Abl = p.Al[br] + bz * p.aBS + (size_t)m0 * K;
    const __nv_bfloat16* Bbh = p.Bh[br] + bz * p.bBS + n0;
    const __nv_bfloat16* Bbl = p.Bl[br] + bz * p.bBS + n0;

    const int a_r = t >> 3, a_c = t & 7;  // A: 1024 16B-chunks / 256 thr = 4 it
    // B: 512 chunks / 256 thr = 2 it

    auto load_chunk = [&](int k0, int stg) {
        const uint32_t st = sb + stg * STG;
#pragma unroll
        for (int it = 0; it < 4; it++) {
            int row = it * 32 + a_r;
            uint32_t d = (uint32_t)SW(row * 128 + a_c * 16);
            size_t so = (size_t)row * K + k0 + a_c * 8;
            cpa16(st + d, Abh + so);
            cpa16(st + OFF_ALO + d, Abl + so);
        }
#pragma unroll
        for (int it = 0; it < 2; it++) {
            int idx = it * 256 + t;
            int row = idx >> 3, nc = idx & 7;
            uint32_t d = (uint32_t)SW(row * 128 + nc * 16);
            size_t so = (size_t)(k0 + row) * N + nc * 8;
            cpa16(st + OFF_BHI + d, Bbh + so);
            cpa16(st + OFF_BLO + d, Bbl + so);
        }
        CP_COMMIT();
    };

    float acc[2][4][4];
#pragma unroll
    for (int i = 0; i < 2; i++)
#pragma unroll
        for (int j = 0; j < 4; j++)
#pragma unroll
            for (int q = 0; q < 4; q++) acc[i][j][q] = 0.f;

    const int la_r = lane & 15, la_k = lane >> 4;
    const int bt_k = ((lane >> 3) & 1) * 8 + (lane & 7);
    const int bt_n = (lane >> 4) * 8;

    const int nc = K / 64;
    load_chunk(0, 0);

    for (int ci = 0; ci < nc; ci++) {
        const int stg = ci & 1;
        CP_WAIT0();
        __syncthreads();
        if (ci + 1 < nc) load_chunk((ci + 1) * 64, stg ^ 1);

        const uint32_t st = sb + stg * STG;
#pragma unroll
        for (int ks = 0; ks < 4; ks++) {
            uint32_t ahi[2][4], alo[2][4], bh[2][4], bl[2][4];
#pragma unroll
            for (int i = 0; i < 2; i++) {
                uint32_t d = (uint32_t)SW((wm0 + 16 * i + la_r) * 128 +
                                          ks * 32 + la_k * 16);
                LDSM4(ahi[i], st + d);
                LDSM4(alo[i], st + OFF_ALO + d);
            }
#pragma unroll
            for (int jj = 0; jj < 2; jj++) {
                uint32_t d = (uint32_t)SW((ks * 16 + bt_k) * 128 +
                                          (wn0 + 16 * jj + bt_n) * 2);
                LDSM4T(bh[jj], st + OFF_BHI + d);
                LDSM4T(bl[jj], st + OFF_BLO + d);
            }
#pragma unroll
            for (int i = 0; i < 2; i++)
#pragma unroll
                for (int j = 0; j < 4; j++)
                    mma16816(acc[i][j], ahi[i], &bh[j >> 1][(j & 1) * 2]);
#pragma unroll
            for (int i = 0; i < 2; i++)
#pragma unroll
                for (int j = 0; j < 4; j++)
                    mma16816(acc[i][j], ahi[i], &bl[j >> 1][(j & 1) * 2]);
#pragma unroll
            for (int i = 0; i < 2; i++)
#pragma unroll
                for (int j = 0; j < 4; j++)
                    mma16816(acc[i][j], alo[i], &bh[j >> 1][(j & 1) * 2]);
        }
        __syncthreads();
    }

    // ---------------- epilogue ----------------
    const int g  = lane >> 2;
    const int t2 = lane & 3;

#pragma unroll
    for (int i = 0; i < 2; i++) {
        const int r0 = m0 + wm0 + 16 * i + g;
        const int r1 = r0 + 8;
        float sc0 = 1.f, sh0 = 0.f, sc1 = 1.f, sh1 = 0.f;
        if (EP == EPL_BNRELU) {
            const float* bnp = p.bn[br];
            float ga = bnp[r0], be = bnp[p.M + r0], mu = bnp[2 * p.M + r0], va = bnp[3 * p.M + r0];
            sc0 = ga * rsqrtf(va + 1e-5f);
            sh0 = be - mu * sc0;
            ga = bnp[r1]; be = bnp[p.M + r1]; mu = bnp[2 * p.M + r1]; va = bnp[3 * p.M + r1];
            sc1 = ga * rsqrtf(va + 1e-5f);
            sh1 = be - mu * sc1;
        }
#pragma unroll
        for (int j = 0; j < 4; j++) {
            const int c = n0 + wn0 + 8 * j + t2 * 2;
            float v0 = acc[i][j][0], v1 = acc[i][j][1];
            float v2 = acc[i][j][2], v3 = acc[i][j][3];
            if (EP == EPL_BNRELU) {
                v0 = fmaxf(v0 * sc0 + sh0, 0.f);
                v1 = fmaxf(v1 * sc0 + sh0, 0.f);
                v2 = fmaxf(v2 * sc1 + sh1, 0.f);
                v3 = fmaxf(v3 * sc1 + sh1, 0.f);
            }
            if (EP == EPF_DIV) {
                const float* zb = p.z[br] + (size_t)bz * N + c;
                float z0 = zb[0], z1 = zb[1];
                float* Cb = p.Cf[br] + bz * p.cBS;
                *(float2*)(Cb + (size_t)r0 * N + c) = make_float2(v0 / z0, v1 / z1);
                *(float2*)(Cb + (size_t)r1 * N + c) = make_float2(v2 / z0, v3 / z1);
            } else {
                uint32_t h0, l0, h1, l1;
                split2(v0, v1, h0, l0);
                split2(v2, v3, h1, l1);
                size_t cb0 = bz * p.cBS + (size_t)r0 * N + c;
                size_t cb1 = bz * p.cBS + (size_t)r1 * N + c;
                *(uint32_t*)(p.Ch[br] + cb0) = h0;
                *(uint32_t*)(p.Cl[br] + cb0) = l0;
                *(uint32_t*)(p.Ch[br] + cb1) = h1;
                *(uint32_t*)(p.Cl[br] + cb1) = l1;
            }
        }
    }
}

// ================= fp32 -> bf16 hi/lo plane conversion ======================
__global__ void to_planes(const float4* __restrict__ src,
                          uint2* __restrict__ hi, uint2* __restrict__ lo, int n4)
{
    int i = blockIdx.x * blockDim.x + threadIdx.x;
    if (i >= n4) return;
    float4 f = src[i];
    uint2 h, l;
    split2(f.x, f.y, h.x, l.x);
    split2(f.z, f.w, h.y, l.y);
    hi[i] = h;
    lo[i] = l;
}

// 3 tensors in one launch (segmented grid)
__global__ void to_planes3(const float4* s0, uint2* h0, uint2* l0, int n0,
                           const float4* s1, uint2* h1, uint2* l1, int n1,
                           const float4* s2, uint2* h2, uint2* l2, int n2)
{
    int i = blockIdx.x * blockDim.x + threadIdx.x;
    const float4* s; uint2 *hp, *lp; int idx;
    if (i < n0)           { s = s0; hp = h0; lp = l0; idx = i; }
    else if (i < n0 + n1) { s = s1; hp = h1; lp = l1; idx = i - n0; }
    else if (i < n0 + n1 + n2) { s = s2; hp = h2; lp = l2; idx = i - n0 - n1; }
    else return;
    float4 f = s[idx];
    uint2 h, l;
    split2(f.x, f.y, h.x, l.x);
    split2(f.z, f.w, h.y, l.y);
    hp[idx] = h;
    lp[idx] = l;
}

// ================= softmax (deterministic, both branches) ===================
__global__ void colmax_part(const __nv_bfloat16* __restrict__ ah, float* __restrict__ pm)
{
    const int zc = blockIdx.z;
    const int tc = blockIdx.x * blockDim.x + threadIdx.x;
    const int kc = blockIdx.y;
    const __nv_bfloat16* p = ah + (size_t)zc * S * S + (size_t)kc * KSEG * S + tc;
    float mx = -3.402823466e38f;
#pragma unroll 8
    for (int k = 0; k < KSEG; k++)
        mx = fmaxf(mx, __bfloat162float(p[(size_t)k * S]));
    pm[(size_t)kc * (NZ * S) + zc * S + tc] = mx;
}

template <bool IS_MAX>
__global__ void reduce_parts(const float* __restrict__ part, float* __restrict__ outv)
{
    const int i = blockIdx.x * blockDim.x + threadIdx.x;
    if (i >= NZ * S) return;
    float v = IS_MAX ? -3.402823466e38f : 0.f;
#pragma unroll
    for (int c = 0; c < KCH; c++) {
        float p = part[(size_t)c * (NZ * S) + i];
        v = IS_MAX ? fmaxf(v, p) : (v + p);
    }
    outv[i] = v;
}

__global__ void expsum_part(__nv_bfloat16* __restrict__ ah, __nv_bfloat16* __restrict__ al,
                            const float* __restrict__ m, float* __restrict__ pz)
{
    const int zc = blockIdx.z;
    const int tc = blockIdx.x * blockDim.x + threadIdx.x;
    const int kc = blockIdx.y;
    const float mv = m[zc * S + tc];
    const size_t base = (size_t)zc * S * S + (size_t)kc * KSEG * S + tc;
    float s = 0.f;
#pragma unroll 4
    for (int k = 0; k < KSEG; k++) {
        size_t idx = base + (size_t)k * S;
        float f = __bfloat162float(ah[idx]) + __bfloat162float(al[idx]);
        float v = __expf(f - mv);
        s += v;
        __nv_bfloat16 vh = __float2bfloat16(v);
        float vr = v - __bfloat162float(vh);
        ah[idx] = vh;
        al[idx] = __float2bfloat16(vr);
    }
    pz[(size_t)kc * (NZ * S) + zc * S + tc] = s;
}

// ================= launch ====================================================
extern "C" void kernel_launch(void* const* d_in, const int* in_sizes, int n_in,
                              void* d_out, int out_size)
{
    (void)in_sizes; (void)n_in; (void)out_size;
    const float* x = (const float*)d_in[0];
    float* out = (float*)d_out;

    __nv_bfloat16 *xh, *xl, *redh, *redl, *hh, *hl, *ah, *al;
    __nv_bfloat16 *wrh, *wrl, *w1h, *w1l, *w2h, *w2l;
    float *m_, *z_, *pm_, *pz_;
    cudaGetSymbolAddress((void**)&xh, g_xh);   cudaGetSymbolAddress((void**)&xl, g_xl);
    cudaGetSymbolAddress((void**)&wrh, g_wrh); cudaGetSymbolAddress((void**)&wrl, g_wrl);
    cudaGetSymbolAddress((void**)&w1h, g_w1h); cudaGetSymbolAddress((void**)&w1l, g_w1l);
    cudaGetSymbolAddress((void**)&w2h, g_w2h); cudaGetSymbolAddress((void**)&w2l, g_w2l);
    cudaGetSymbolAddress((void**)&redh, g_redh); cudaGetSymbolAddress((void**)&redl, g_redl);
    cudaGetSymbolAddress((void**)&hh, g_hh);   cudaGetSymbolAddress((void**)&hl, g_hl);
    cudaGetSymbolAddress((void**)&ah, g_ah);   cudaGetSymbolAddress((void**)&al, g_al);
    cudaGetSymbolAddress((void**)&m_, g_m);    cudaGetSymbolAddress((void**)&z_, g_z);
    cudaGetSymbolAddress((void**)&pm_, g_pm);  cudaGetSymbolAddress((void**)&pz_, g_pz);

    const size_t WR = (size_t)RC * CIN, W1 = (size_t)RC * RC, W2 = (size_t)OC * RC;

    cudaFuncSetAttribute(gemm_mma<EPL_BNRELU>, cudaFuncAttributeMaxDynamicSharedMemorySize, SMEM_BYTES);
    cudaFuncSetAttribute(gemm_mma<EPL_PLAIN>,  cudaFuncAttributeMaxDynamicSharedMemorySize, SMEM_BYTES);
    cudaFuncSetAttribute(gemm_mma<EPF_DIV>,    cudaFuncAttributeMaxDynamicSharedMemorySize, SMEM_BYTES);

    // [0] x -> planes
    {
        int n4 = NB * CIN * S / 4;
        to_planes<<<(n4 + 255) / 256, 256>>>((const float4*)x, (uint2*)xh, (uint2*)xl, n4);
    }
    // [1],[2] weights -> planes (one launch per branch)
    for (int br = 0; br < 2; br++) {
        const float* wred = (const float*)d_in[1 + br * 5 + 0];
        const float* w1   = (const float*)d_in[1 + br * 5 + 2];
        const float* w2   = (const float*)d_in[1 + br * 5 + 4];
        int n0 = (int)(WR / 4), n1 = (int)(W1 / 4), n2 = (int)(W2 / 4);
        int nb = (n0 + n1 + n2 + 255) / 256;
        to_planes3<<<nb, 256>>>(
            (const float4*)wred, (uint2*)(wrh + br * WR), (uint2*)(wrl + br * WR), n0,
            (const float4*)w1,   (uint2*)(w1h + br * W1), (uint2*)(w1l + br * W1), n1,
            (const float4*)w2,   (uint2*)(w2h + br * W2), (uint2*)(w2l + br * W2), n2);
    }

    const float* bn1c = (const float*)d_in[2];
    const float* bn2c = (const float*)d_in[4];
    const float* bn1d = (const float*)d_in[7];
    const float* bn2d = (const float*)d_in[9];

    GP p{};
    // [3] reduce: red = relu(bn1(wred @ x))
    p.Ah[0] = wrh; p.Ah[1] = wrh + WR; p.Al[0] = wrl; p.Al[1] = wrl + WR;
    p.Bh[0] = p.Bh[1] = xh; p.Bl[0] = p.Bl[1] = xl;
    p.Ch[0] = redh; p.Ch[1] = redh + (size_t)NB * RC * S;
    p.Cl[0] = redl; p.Cl[1] = redl + (size_t)NB * RC * S;
    p.bn[0] = bn1c; p.bn[1] = bn1d;
    p.M = RC; p.K = CIN; p.N = S;
    p.aBS = 0; p.bBS = (size_t)CIN * S; p.cBS = (size_t)RC * S;
    gemm_mma<EPL_BNRELU><<<dim3(S / 64, RC / 128, NZ), 256, SMEM_BYTES>>>(p);

    // [4] conv1: h = relu(bn2(w1 @ red))
    p.Ah[0] = w1h; p.Ah[1] = w1h + W1; p.Al[0] = w1l; p.Al[1] = w1l + W1;
    p.Bh[0] = redh; p.Bh[1] = redh + (size_t)NB * RC * S;
    p.Bl[0] = redl; p.Bl[1] = redl + (size_t)NB * RC * S;
    p.Ch[0] = hh; p.Ch[1] = hh + (size_t)NB * RC * S;
    p.Cl[0] = hl; p.Cl[1] = hl + (size_t)NB * RC * S;
    p.bn[0] = bn2c; p.bn[1] = bn2d;
    p.M = RC; p.K = RC; p.N = S;
    p.aBS = 0; p.bBS = (size_t)RC * S; p.cBS = (size_t)RC * S;
    gemm_mma<EPL_BNRELU><<<dim3(S / 64, RC / 128, NZ), 256, SMEM_BYTES>>>(p);

    // [5] conv2: a = w2 @ h      <-- ncu target
    p.Ah[0] = w2h; p.Ah[1] = w2h + W2; p.Al[0] = w2l; p.Al[1] = w2l + W2;
    p.Bh[0] = hh; p.Bh[1] = hh + (size_t)NB * RC * S;
    p.Bl[0] = hl; p.Bl[1] = hl + (size_t)NB * RC * S;
    p.Ch[0] = ah; p.Ch[1] = ah + (size_t)NB * OC * S;
    p.Cl[0] = al; p.Cl[1] = al + (size_t)NB * OC * S;
    p.M = OC; p.K = RC; p.N = S;
    p.aBS = 0; p.bBS = (size_t)RC * S; p.cBS = (size_t)OC * S;
    gemm_mma<EPL_PLAIN><<<dim3(S / 64, OC / 128, NZ), 256, SMEM_BYTES>>>(p);

    // [6..9] deterministic column softmax over both branches
    colmax_part<<<dim3(S / 256, KCH, NZ), 256>>>(ah, pm_);
    reduce_parts<true><<<(NZ * S + 255) / 256, 256>>>(pm_, m_);
    expsum_part<<<dim3(S / 256, KCH, NZ), 256>>>(ah, al, m_, pz_);
    reduce_parts<false><<<(NZ * S + 255) / 256, 256>>>(pz_, z_);

    // [10] bmm: fm = red @ exp(a-m) / Z  -> out
    p.Ah[0] = redh; p.Ah[1] = redh + (size_t)NB * RC * S;
    p.Al[0] = redl; p.Al[1] = redl + (size_t)NB * RC * S;
    p.Bh[0] = ah; p.Bh[1] = ah + (size_t)NB * OC * S;
    p.Bl[0] = al; p.Bl[1] = al + (size_t)NB * OC * S;
    p.Cf[0] = out; p.Cf[1] = out + (size_t)RC * S;
    p.z[0] = z_; p.z[1] = z_ + (size_t)NB * S;
    p.M = RC; p.K = S; p.N = S;
    p.aBS = (size_t)RC * S; p.bBS = (size_t)S * S; p.cBS = (size_t)2 * RC * S;
    gemm_mma<EPF_DIV><<<dim3(S / 64, RC / 128, NZ), 256, SMEM_BYTES>>>(p);
}